// round 13
// baseline (speedup 1.0000x reference)
#include <cuda_runtime.h>
#include <cuda_fp16.h>
#include <math.h>
#include <stdint.h>

#define BB 64
#define LL 2048
#define TT 1024
#define DD 128
#define EE 512
#define HH 8
#define PP 3
#define HP 24
#define LAT 256
#define HID 512
#define NSIN 64
#define SPL 8
#define LSP (LL/SPL)
#define NKC2 8           // mlp2: K=512 in chunks of 64
#define NKC3 8           // mlp3: K=512 in chunks of 64
#define ROWB 144         // A/B smem row bytes (64 fp16 + 8 pad)

// ---------------- static device scratch (no allocations) ----------------
__device__ float g_q[PP*EE];
__device__ float g_A[EE*HP];
__device__ float g_lin[HP];
__device__ float g_off[HP];
__device__ float g_bound[HP];
__device__ float g_ws[NSIN];
__device__ float g_bs[NSIN];
__device__ float g_Asin[NSIN*HP];
__device__ float g_bcp[8*LAT];
__device__ float g_part[SPL*BB*HP*256];
__device__ float g_Dm[BB*3*HID];
__device__ __align__(16) __half g_B2[512*512];               // W2 fp16, [n][k]
__device__ __align__(16) __half g_B3[128*512];               // W3 fp16, [n][k]
__device__ __align__(16) __half g_H2[(size_t)BB*TT*HID];     // relu(h1@W2+b2) fp16

// ---------------- PTX helpers -------------------------------------------
__device__ __forceinline__ uint32_t smem_u32(const void* p) {
    uint32_t a;
    asm("{ .reg .u64 t; cvta.to.shared.u64 t, %1; cvt.u32.u64 %0, t; }"
        : "=r"(a) : "l"(p));
    return a;
}
__device__ __forceinline__ uint32_t pack2h(float a, float b) {
    __half2 h = __floats2half2_rn(a, b);
    return *reinterpret_cast<uint32_t*>(&h);
}
// sin via pi-reduction + deg-11 odd Taylor; |err| < 1e-7 for |x| < ~6
__device__ __forceinline__ float sin_poly(float x) {
    float xn = rintf(x * 0.31830988618f);
    float xr = fmaf(xn, -3.14159274f, x);
    xr = fmaf(xn, 8.742278e-8f, xr);
    float x2 = xr * xr;
    float p = -2.50521084e-8f;
    p = fmaf(p, x2, 2.75573192e-6f);
    p = fmaf(p, x2, -1.98412698e-4f);
    p = fmaf(p, x2, 8.33333333e-3f);
    p = fmaf(p, x2, -1.66666667e-1f);
    float s = xr * fmaf(p, x2, 1.0f);
    int ni = (int)xn;
    return __int_as_float(__float_as_int(s) ^ ((ni & 1) << 31));
}

#define CP16(dst, src) \
    asm volatile("cp.async.cg.shared.global [%0], [%1], 16;" :: "r"(dst), "l"(src))
#define CP_COMMIT() asm volatile("cp.async.commit_group;" ::: "memory")
#define CP_WAIT(n)  asm volatile("cp.async.wait_group %0;" :: "n"(n) : "memory")

#define LDM_X4(r, addr) \
    asm volatile("ldmatrix.sync.aligned.m8n8.x4.shared.b16 {%0,%1,%2,%3}, [%4];" \
        : "=r"((r)[0]), "=r"((r)[1]), "=r"((r)[2]), "=r"((r)[3]) : "r"(addr))

#define MMA16816(c, a, b0, b1) \
    asm volatile("mma.sync.aligned.m16n8k16.row.col.f32.f16.f16.f32 " \
        "{%0,%1,%2,%3}, {%4,%5,%6,%7}, {%8,%9}, {%0,%1,%2,%3};" \
        : "+f"((c)[0]), "+f"((c)[1]), "+f"((c)[2]), "+f"((c)[3]) \
        : "r"((a)[0]), "r"((a)[1]), "r"((a)[2]), "r"((a)[3]), "r"(b0), "r"(b1))

// ---------------- setup kernels -----------------------------------------
__global__ void k_setup_q(const float* __restrict__ query,
                          const float* __restrict__ W_q,
                          const float* __restrict__ b_q) {
    int idx = blockIdx.x * 256 + threadIdx.x;   // < 1536
    int p = idx / EE, e = idx % EE;
    float acc = b_q[e];
    for (int i = 0; i < EE; i++)
        acc = fmaf(query[p*EE + i], W_q[i*EE + e], acc);
    g_q[idx] = acc;
}

__global__ void k_setup_A(const float* __restrict__ W_k) {
    int idx = blockIdx.x * 256 + threadIdx.x;   // < 12288
    int e = idx / HP, hp = idx % HP;
    int h = hp / PP, p = hp % PP;
    float acc = 0.f;
    #pragma unroll 4
    for (int j = 0; j < 64; j++)
        acc = fmaf(W_k[e*EE + h*64 + j], g_q[p*EE + h*64 + j], acc);
    g_A[idx] = acc * 0.125f;
}

__global__ void k_setup_misc(const float* __restrict__ b_k,
                             const float* __restrict__ w_te,
                             const float* __restrict__ b_te) {
    int tid = threadIdx.x;
    int bid = blockIdx.x;
    if (bid == 0) {
        if (tid < HP) {
            int hp = tid, h = hp / PP, p = hp % PP;
            float lin = 0.f, off = 0.f;
            for (int j = 0; j < 64; j++)
                off = fmaf(g_q[p*EE + h*64 + j], b_k[h*64 + j], off);
            off *= 0.125f;
            for (int e = 0; e < EE; e++) {
                if ((e & 7) != 0) {
                    float a = g_A[e*HP + hp];
                    lin = fmaf(w_te[e], a, lin);
                    off = fmaf(b_te[e], a, off);
                }
            }
            g_lin[hp] = lin; g_off[hp] = off;
            float bnd = off + fmaxf(lin, 0.f);
            for (int j = 0; j < NSIN; j++)
                bnd += fabsf(g_A[(8*j)*HP + hp]);
            g_bound[hp] = bnd;
        }
        if (tid < NSIN) { g_ws[tid] = w_te[8*tid]; g_bs[tid] = b_te[8*tid]; }
    } else {
        for (int idx = tid; idx < NSIN*HP; idx += 256) {
            int j = idx / HP, hp = idx % HP;
            g_Asin[idx] = g_A[(8*j)*HP + hp];
        }
    }
}

// ---------------- bconst partials ---------------------------------------
__global__ void k_bcpart(const float* __restrict__ W_o) {
    int h = blockIdx.x;           // 0..7
    int n = threadIdx.x;          // 0..255
    float acc = 0.f;
    const float* base = W_o + (size_t)(h*256 + 128)*LAT + n;
    #pragma unroll 8
    for (int c = 0; c < DD; c++)
        acc += base[(size_t)c*LAT];
    g_bcp[h*LAT + n] = acc;
}

// ---------------- W2/W3 fp16 prep (smem-tiled transpose) ----------------
__global__ void k_prepW(const float* __restrict__ W2,
                        const float* __restrict__ W3) {
    __shared__ float s_tile[64][65];
    int bid = blockIdx.x;         // 0..79
    int tid = threadIdx.x;
    int c = tid & 63, rloc = tid >> 6;

    const float* src;
    int tk, tn, src_cols;
    bool isW2 = (bid < 64);
    if (isW2) { tk = bid >> 3; tn = bid & 7; src = W2; src_cols = 512; }
    else      { int l = bid - 64; tk = l >> 1; tn = l & 1; src = W3; src_cols = 128; }

    #pragma unroll
    for (int i = 0; i < 16; i++) {
        int row = rloc + i*4;
        s_tile[row][c] = src[(size_t)(tk*64 + row)*src_cols + tn*64 + c];
    }
    __syncthreads();
    #pragma unroll
    for (int i = 0; i < 16; i++) {
        int n = rloc + i*4;
        __half h = __float2half_rn(s_tile[c][n]);
        if (isW2) g_B2[(size_t)(tn*64 + n)*512 + tk*64 + c] = h;
        else      g_B3[(size_t)(tn*64 + n)*512 + tk*64 + c] = h;
    }
}

// ---------------- K3: attention partials (scores fused in) --------------
__global__ void k_att_partial(const float* __restrict__ X,
                              const float* __restrict__ M,
                              const float* __restrict__ timesteps) {
    __shared__ float s_Asin[NSIN*HP];          // [j][hp]
    __shared__ float s_lin[HP], s_off[HP], s_m[HP];
    __shared__ float s_ws[NSIN], s_bs[NSIN];
    __shared__ float s_t[64];
    __shared__ float s_sin[64*65];             // [li][j], pitch 65
    __shared__ __align__(16) float s_w[64*HP];
    int tid = threadIdx.x;
    int b  = blockIdx.x / SPL;
    int sp = blockIdx.x % SPL;
    int l0 = sp * LSP;
    for (int i = tid; i < NSIN*HP; i += 256) s_Asin[i] = g_Asin[i];
    if (tid < HP) { s_lin[tid] = g_lin[tid]; s_off[tid] = g_off[tid]; s_m[tid] = g_bound[tid]; }
    if (tid < NSIN) { s_ws[tid] = g_ws[tid]; s_bs[tid] = g_bs[tid]; }
    float acc[HP];
    #pragma unroll
    for (int hp = 0; hp < HP; hp++) acc[hp] = 0.f;
    int c = tid;
    int li64 = tid & 63, jg = tid >> 6;

    for (int ch = 0; ch < LSP; ch += 64) {
        if (tid < 64) s_t[tid] = timesteps[b*LL + l0 + ch + tid];
        __syncthreads();
        // stage 1: sins (each thread: one li, 16 j)
        {
            float t = s_t[li64];
            #pragma unroll
            for (int jj = 0; jj < 16; jj++) {
                int j = jg*16 + jj;
                s_sin[li64*65 + j] = sin_poly(fmaf(t, s_ws[j], s_bs[j]));
            }
        }
        __syncthreads();
        // stage 2: w fill (1536 values)
        #pragma unroll
        for (int r = 0; r < 6; r++) {
            int i = tid + r*256;
            int li = i / HP, hp = i % HP;
            float a = fmaf(s_t[li], s_lin[hp], s_off[hp]) - s_m[hp];
            const float* srow = &s_sin[li*65];
            #pragma unroll 8
            for (int j = 0; j < NSIN; j++)
                a = fmaf(srow[j], s_Asin[j*HP + hp], a);
            s_w[i] = __expf(a);
        }
        __syncthreads();
        // stage 3: accumulate
        #pragma unroll 4
        for (int li = 0; li < 64; li++) {
            int l = l0 + ch + li;
            float f;
            if (c < DD) {
                float xv = X[((long)b*LL + l)*DD + c];
                float mv = M[((long)b*LL + l)*DD + c];
                f = xv * mv;
            } else {
                f = M[((long)b*LL + l)*DD + (c - DD)];
            }
            const float4* w4 = reinterpret_cast<const float4*>(&s_w[li*HP]);
            float4 w0 = w4[0], w1 = w4[1], w2 = w4[2];
            float4 w3 = w4[3], w4v = w4[4], w5 = w4[5];
            acc[0]  = fmaf(w0.x,  f, acc[0]);  acc[1]  = fmaf(w0.y,  f, acc[1]);
            acc[2]  = fmaf(w0.z,  f, acc[2]);  acc[3]  = fmaf(w0.w,  f, acc[3]);
            acc[4]  = fmaf(w1.x,  f, acc[4]);  acc[5]  = fmaf(w1.y,  f, acc[5]);
            acc[6]  = fmaf(w1.z,  f, acc[6]);  acc[7]  = fmaf(w1.w,  f, acc[7]);
            acc[8]  = fmaf(w2.x,  f, acc[8]);  acc[9]  = fmaf(w2.y,  f, acc[9]);
            acc[10] = fmaf(w2.z,  f, acc[10]); acc[11] = fmaf(w2.w,  f, acc[11]);
            acc[12] = fmaf(w3.x,  f, acc[12]); acc[13] = fmaf(w3.y,  f, acc[13]);
            acc[14] = fmaf(w3.z,  f, acc[14]); acc[15] = fmaf(w3.w,  f, acc[15]);
            acc[16] = fmaf(w4v.x, f, acc[16]); acc[17] = fmaf(w4v.y, f, acc[17]);
            acc[18] = fmaf(w4v.z, f, acc[18]); acc[19] = fmaf(w4v.w, f, acc[19]);
            acc[20] = fmaf(w5.x,  f, acc[20]); acc[21] = fmaf(w5.y,  f, acc[21]);
            acc[22] = fmaf(w5.z,  f, acc[22]); acc[23] = fmaf(w5.w,  f, acc[23]);
        }
        __syncthreads();
    }
    for (int hp = 0; hp < HP; hp++)
        g_part[(((sp*BB) + b)*HP + hp)*256 + c] = acc[hp];
}

// ---------------- K5: x1 (fused reduce), coeffs, D-matrices -------------
__global__ void k_coeffs(const float* __restrict__ W_o,
                         const float* __restrict__ W1,
                         const float* __restrict__ b1,
                         const float* __restrict__ b_o) {
    __shared__ float s_x1[HP*DD];
    __shared__ float s_cf[PP*LAT];
    int tid = threadIdx.x;
    int b = blockIdx.x;
    for (int i = tid; i < HP*DD; i += 256) {
        int hp = i / DD, c = i % DD;
        float num = 0.f, den = 0.f;
        #pragma unroll
        for (int sp = 0; sp < SPL; sp++) {
            int base = (((sp*BB) + b)*HP + hp)*256;
            num += g_part[base + c];
            den += g_part[base + 128 + c];
        }
        s_x1[i] = num / den;
    }
    __syncthreads();
    {
        int n = tid;
        float bc = b_o[n];
        #pragma unroll
        for (int j = 0; j < 8; j++) bc += g_bcp[j*LAT + n];
        float a0 = bc, a1 = bc, a2 = bc;
        for (int h = 0; h < HH; h++) {
            #pragma unroll 4
            for (int c = 0; c < DD; c++) {
                float wv = W_o[(h*256 + c)*LAT + n];
                a0 = fmaf(s_x1[(h*PP + 0)*DD + c], wv, a0);
                a1 = fmaf(s_x1[(h*PP + 1)*DD + c], wv, a1);
                a2 = fmaf(s_x1[(h*PP + 2)*DD + c], wv, a2);
            }
        }
        s_cf[0*LAT + n] = a0; s_cf[1*LAT + n] = a1; s_cf[2*LAT + n] = a2;
    }
    __syncthreads();
    for (int idx = tid; idx < 3*HID; idx += 256) {
        int k = idx / HID, j = idx % HID;
        float acc = (k == 0) ? b1[j] : 0.f;
        #pragma unroll 4
        for (int n = 0; n < LAT; n++)
            acc = fmaf(s_cf[k*LAT + n], W1[n*HID + j], acc);
        g_Dm[(b*3 + k)*HID + j] = acc;
    }
}

// ---------------- mma compute: one K=64 chunk (low reg pressure) --------
__device__ __forceinline__ void mma_chunk64(
    float acc[2][8][4], uint32_t asb, uint32_t bsb,
    int m0w, int n0w, int lane)
{
    #pragma unroll
    for (int ks = 0; ks < 4; ks++) {
        uint32_t a[2][4];
        #pragma unroll
        for (int mi = 0; mi < 2; mi++) {
            uint32_t ad = asb + (uint32_t)(m0w + mi*16 + (lane & 15)) * ROWB
                        + (uint32_t)(ks*32 + ((lane >> 4) << 4));
            LDM_X4(a[mi], ad);
        }
        #pragma unroll
        for (int nt = 0; nt < 4; nt++) {
            uint32_t bf[4];
            int rown = n0w + nt*16 + ((lane >> 4) << 3) + (lane & 7);
            uint32_t bd = bsb + (uint32_t)rown * ROWB
                        + (uint32_t)(ks*32 + (((lane >> 3) & 1) << 4));
            LDM_X4(bf, bd);
            MMA16816(acc[0][2*nt],     a[0], bf[0], bf[1]);
            MMA16816(acc[0][2*nt + 1], a[0], bf[2], bf[3]);
            MMA16816(acc[1][2*nt],     a[1], bf[0], bf[1]);
            MMA16816(acc[1][2*nt + 1], a[1], bf[2], bf[3]);
        }
    }
}

// ---------------- K6: W2 GEMM, single fp16, K=512 -----------------------
// dyn smem: 0 s_t(512) | 512 s_b2(512) | 1024 s_D(6144) |
// 7168 A bufs 2x18432 | 44032 B bufs 2x18432 | total 80896
#define SM2_DYN 80896

__global__ void __launch_bounds__(256, 2)
k_mlp2m(const float* __restrict__ yts, const float* __restrict__ b2) {
    extern __shared__ char sm[];
    float* s_t  = (float*)(sm);
    float* s_b2 = (float*)(sm + 512);
    float* s_D  = (float*)(sm + 1024);

    int tid = threadIdx.x, lane = tid & 31, wid = tid >> 5;
    int m0 = blockIdx.x * 128;
    int n0 = blockIdx.y * 128;
    int b = m0 >> 10;
    int m0w = (wid & 3) * 32;
    int n0w = (wid >> 2) * 64;

    if (tid < 128) s_t[tid] = yts[b*TT + (m0 & 1023) + tid];
    for (int i = tid; i < 3*HID; i += 256) s_D[i] = g_Dm[b*3*HID + i];
    if (tid < 128) s_b2[tid] = b2[n0 + tid];
    __syncthreads();

    uint32_t sb = smem_u32(sm);
    uint32_t as0 = sb + 7168, as1 = sb + 7168 + 18432;
    uint32_t bs0 = sb + 44032, bs1 = sb + 44032 + 18432;

    int grow = tid >> 1;
    int gkh  = (tid & 1) << 5;          // 0/32 within 64-k chunk
    float t = s_t[grow];

    float acc[2][8][4];
    #pragma unroll
    for (int mi = 0; mi < 2; mi++)
        #pragma unroll
        for (int nj = 0; nj < 8; nj++)
            #pragma unroll
            for (int q = 0; q < 4; q++) acc[mi][nj][q] = 0.f;

    // A = fp16(relu(D0 + t D1 + t^2 D2)), generated in 4-reg groups
    auto genA = [&](int kk, uint32_t asb) {
        int kloc = (kk << 6) + gkh;
        uint32_t d = asb + (uint32_t)grow*ROWB + (uint32_t)(gkh << 1);
        #pragma unroll
        for (int g4 = 0; g4 < 4; g4++) {
            uint32_t p[4];
            #pragma unroll
            for (int j2 = 0; j2 < 4; j2++) {
                float f[2];
                #pragma unroll
                for (int q = 0; q < 2; q++) {
                    int k = kloc + (g4*4 + j2)*2 + q;
                    float v = fmaf(t, fmaf(t, s_D[1024 + k], s_D[512 + k]), s_D[k]);
                    f[q] = fmaxf(v, 0.f);
                }
                p[j2] = pack2h(f[0], f[1]);
            }
            asm volatile("st.shared.v4.b32 [%0], {%1,%2,%3,%4};"
                         :: "r"(d + g4*16), "r"(p[0]), "r"(p[1]), "r"(p[2]), "r"(p[3]));
        }
    };
    auto loadB = [&](int kk, uint32_t bsb) {
        #pragma unroll
        for (int i = 0; i < 4; i++) {
            int u = tid + (i << 8);
            int n = u >> 3, q = u & 7;
            uint32_t d = bsb + (uint32_t)n*ROWB + (uint32_t)(q << 4);
            const char* s = (const char*)g_B2
                + ((size_t)(n0 + n)*512 + (size_t)kk*64)*2 + q*16;
            CP16(d, s);
        }
    };

    genA(0, as0); loadB(0, bs0); CP_COMMIT();
    for (int kk = 0; kk < NKC2; kk++) {
        int buf = kk & 1;
        if (kk + 1 < NKC2) {
            genA(kk + 1, buf ? as0 : as1);
            loadB(kk + 1, buf ? bs0 : bs1);
            CP_COMMIT();
            CP_WAIT(1);
        } else {
            CP_WAIT(0);
        }
        __syncthreads();
        mma_chunk64(acc, buf ? as1 : as0, buf ? bs1 : bs0, m0w, n0w, lane);
        __syncthreads();
    }

    // ---- epilogue: relu+bias -> fp16, smem-staged coalesced stores ----
    char* stg = sm + 7168;                   // reuse A-buf region
    const int PADR = 136;
    #pragma unroll
    for (int mi = 0; mi < 2; mi++) {
        #pragma unroll
        for (int nj = 0; nj < 8; nj++) {
            int cl = n0w + nj*8 + (lane & 3)*2;
            #pragma unroll
            for (int half = 0; half < 2; half++) {
                int r = m0w + mi*16 + (lane >> 2) + half*8;
                float f0 = fmaxf(acc[mi][nj][half*2 + 0] + s_b2[cl], 0.f);
                float f1 = fmaxf(acc[mi][nj][half*2 + 1] + s_b2[cl + 1], 0.f);
                *reinterpret_cast<uint32_t*>(stg + (r*PADR + cl)*2) = pack2h(f0, f1);
            }
        }
    }
    __syncthreads();
    #pragma unroll
    for (int ps = 0; ps < 8; ps++) {
        int u = ps*256 + tid;
        int row = u >> 4, ch = u & 15;
        uint4 v = *reinterpret_cast<uint4*>(stg + row*PADR*2 + ch*16);
        *reinterpret_cast<uint4*>((char*)g_H2 + ((size_t)(m0 + row)*HID + n0)*2 + ch*16) = v;
    }
}

// ---------------- K7: W3 GEMM, single fp16, K=512 -----------------------
// dyn smem: 0 s_b3(512) | 512 A bufs 2x18432 | 37376 B bufs 2x18432
// total 74240
#define SM3_DYN 74240

__global__ void __launch_bounds__(256, 2)
k_mlp3m(const float* __restrict__ b3, float* __restrict__ out) {
    extern __shared__ char sm[];
    float* s_b3 = (float*)(sm);

    int tid = threadIdx.x, lane = tid & 31, wid = tid >> 5;
    int m0 = blockIdx.x * 128;
    int m0w = (wid & 3) * 32;
    int n0w = (wid >> 2) * 64;

    if (tid < 128) s_b3[tid] = b3[tid];
    __syncthreads();

    uint32_t sb = smem_u32(sm);
    uint32_t as0 = sb + 512, as1 = sb + 512 + 18432;
    uint32_t bs0 = sb + 37376, bs1 = sb + 37376 + 18432;

    float acc[2][8][4];
    #pragma unroll
    for (int mi = 0; mi < 2; mi++)
        #pragma unroll
        for (int nj = 0; nj < 8; nj++)
            #pragma unroll
            for (int q = 0; q < 4; q++) acc[mi][nj][q] = 0.f;

    auto loadA = [&](int i, uint32_t asb) {
        int k0 = i << 6;
        #pragma unroll
        for (int q2 = 0; q2 < 4; q2++) {
            int u = tid + (q2 << 8);
            int row = u >> 3, q = u & 7;
            uint32_t d = asb + (uint32_t)row*ROWB + (uint32_t)(q << 4);
            const char* s = (const char*)g_H2 + ((size_t)(m0 + row)*HID + k0)*2 + q*16;
            CP16(d, s);
        }
    };
    auto loadB = [&](int i, uint32_t bsb) {
        int k0 = i << 6;
        #pragma unroll
        for (int q2 = 0; q2 < 4; q2++) {
            int u = tid + (q2 << 8);
            int n = u >> 3, q = u & 7;
            uint32_t d = bsb + (uint32_t)n*ROWB + (uint32_t)(q << 4);
            const char* s = (const char*)g_B3 + ((size_t)n*512 + k0)*2 + q*16;
            CP16(d, s);
        }
    };

    loadA(0, as0); loadB(0, bs0); CP_COMMIT();
    for (int i = 0; i < NKC3; i++) {
        int buf = i & 1;
        if (i + 1 < NKC3) {
            loadA(i + 1, buf ? as0 : as1);
            loadB(i + 1, buf ? bs0 : bs1);
            CP_COMMIT();
            CP_WAIT(1);
        } else {
            CP_WAIT(0);
        }
        __syncthreads();
        mma_chunk64(acc, buf ? as1 : as0, buf ? bs1 : bs0, m0w, n0w, lane);
        __syncthreads();
    }

    #pragma unroll
    for (int mi = 0; mi < 2; mi++) {
        #pragma unroll
        for (int nj = 0; nj < 8; nj++) {
            int cl = n0w + nj*8 + (lane & 3)*2;
            int rg = m0 + m0w + mi*16 + (lane >> 2);
            #pragma unroll
            for (int half = 0; half < 2; half++) {
                int r = rg + half*8;
                float2 v;
                v.x = acc[mi][nj][half*2 + 0] + s_b3[cl];
                v.y = acc[mi][nj][half*2 + 1] + s_b3[cl + 1];
                *reinterpret_cast<float2*>(&out[(size_t)r*DD + cl]) = v;
            }
        }
    }
}

// ---------------- launch -------------------------------------------------
extern "C" void kernel_launch(void* const* d_in, const int* in_sizes, int n_in,
                              void* d_out, int out_size) {
    const float* timesteps = (const float*)d_in[0];
    const float* X         = (const float*)d_in[1];
    const float* M         = (const float*)d_in[2];
    const float* yts       = (const float*)d_in[3];
    const float* w_te      = (const float*)d_in[4];
    const float* b_te      = (const float*)d_in[5];
    const float* query     = (const float*)d_in[6];
    const float* W_q       = (const float*)d_in[7];
    const float* b_q       = (const float*)d_in[8];
    const float* W_k       = (const float*)d_in[9];
    const float* b_k       = (const float*)d_in[10];
    const float* W_o       = (const float*)d_in[11];
    const float* b_o       = (const float*)d_in[12];
    const float* W1        = (const float*)d_in[13];
    const float* b1        = (const float*)d_in[14];
    const float* W2        = (const float*)d_in[15];
    const float* b2        = (const float*)d_in[16];
    const float* W3        = (const float*)d_in[17];
    const float* b3        = (const float*)d_in[18];
    float* out = (float*)d_out;

    cudaFuncSetAttribute(k_mlp2m, cudaFuncAttributeMaxDynamicSharedMemorySize, SM2_DYN);
    cudaFuncSetAttribute(k_mlp3m, cudaFuncAttributeMaxDynamicSharedMemorySize, SM3_DYN);

    k_setup_q<<<6, 256>>>(query, W_q, b_q);
    k_prepW<<<80, 256>>>(W2, W3);
    k_bcpart<<<8, 256>>>(W_o);
    k_setup_A<<<48, 256>>>(W_k);
    k_setup_misc<<<2, 256>>>(b_k, w_te, b_te);
    k_att_partial<<<SPL*BB, 256>>>(X, M, timesteps);
    k_coeffs<<<BB, 256>>>(W_o, W1, b1, b_o);
    k_mlp2m<<<dim3(BB*TT/128, 4), 256, SM2_DYN>>>(yts, b2);
    k_mlp3m<<<BB*TT/128, 256, SM3_DYN>>>(b3, out);
}

// round 14
// speedup vs baseline: 1.0596x; 1.0596x over previous
#include <cuda_runtime.h>
#include <cuda_fp16.h>
#include <math.h>
#include <stdint.h>

#define BB 64
#define LL 2048
#define TT 1024
#define DD 128
#define EE 512
#define HH 8
#define PP 3
#define HP 24
#define LAT 256
#define HID 512
#define NSIN 64
#define SPL 8
#define LSP (LL/SPL)
#define NKC2 8           // mlp2: K=512 in chunks of 64
#define NKC3 8           // mlp3: K=512 in chunks of 64
#define ROWB 144         // A/B smem row bytes (64 fp16 + 8 pad)
#define SPITCH 68        // s_sin row pitch (floats): 16B-aligned rows

// ---------------- static device scratch (no allocations) ----------------
__device__ float g_q[PP*EE];
__device__ float g_A[EE*HP];
__device__ float g_lin[HP];
__device__ float g_off[HP];
__device__ float g_bound[HP];
__device__ float g_ws[NSIN];
__device__ float g_bs[NSIN];
__device__ float g_Asin[NSIN*HP];
__device__ float g_bcp[8*LAT];
__device__ float g_part[SPL*BB*HP*256];
__device__ float g_Dm[BB*3*HID];
__device__ __align__(16) __half g_B2[512*512];               // W2 fp16, [n][k]
__device__ __align__(16) __half g_B3[128*512];               // W3 fp16, [n][k]
__device__ __align__(16) __half g_H2[(size_t)BB*TT*HID];     // relu(h1@W2+b2) fp16

// ---------------- PTX helpers -------------------------------------------
__device__ __forceinline__ uint32_t smem_u32(const void* p) {
    uint32_t a;
    asm("{ .reg .u64 t; cvta.to.shared.u64 t, %1; cvt.u32.u64 %0, t; }"
        : "=r"(a) : "l"(p));
    return a;
}
__device__ __forceinline__ uint32_t pack2h(float a, float b) {
    __half2 h = __floats2half2_rn(a, b);
    return *reinterpret_cast<uint32_t*>(&h);
}
// sin via pi-reduction + deg-11 odd Taylor; |err| < 1e-7 for |x| < ~6
__device__ __forceinline__ float sin_poly(float x) {
    float xn = rintf(x * 0.31830988618f);
    float xr = fmaf(xn, -3.14159274f, x);
    xr = fmaf(xn, 8.742278e-8f, xr);
    float x2 = xr * xr;
    float p = -2.50521084e-8f;
    p = fmaf(p, x2, 2.75573192e-6f);
    p = fmaf(p, x2, -1.98412698e-4f);
    p = fmaf(p, x2, 8.33333333e-3f);
    p = fmaf(p, x2, -1.66666667e-1f);
    float s = xr * fmaf(p, x2, 1.0f);
    int ni = (int)xn;
    return __int_as_float(__float_as_int(s) ^ ((ni & 1) << 31));
}

#define CP16(dst, src) \
    asm volatile("cp.async.cg.shared.global [%0], [%1], 16;" :: "r"(dst), "l"(src))
#define CP_COMMIT() asm volatile("cp.async.commit_group;" ::: "memory")
#define CP_WAIT(n)  asm volatile("cp.async.wait_group %0;" :: "n"(n) : "memory")

#define LDM_X4(r, addr) \
    asm volatile("ldmatrix.sync.aligned.m8n8.x4.shared.b16 {%0,%1,%2,%3}, [%4];" \
        : "=r"((r)[0]), "=r"((r)[1]), "=r"((r)[2]), "=r"((r)[3]) : "r"(addr))

#define MMA16816(c, a, b0, b1) \
    asm volatile("mma.sync.aligned.m16n8k16.row.col.f32.f16.f16.f32 " \
        "{%0,%1,%2,%3}, {%4,%5,%6,%7}, {%8,%9}, {%0,%1,%2,%3};" \
        : "+f"((c)[0]), "+f"((c)[1]), "+f"((c)[2]), "+f"((c)[3]) \
        : "r"((a)[0]), "r"((a)[1]), "r"((a)[2]), "r"((a)[3]), "r"(b0), "r"(b1))

// ---------------- setup kernels -----------------------------------------
__global__ void k_setup_q(const float* __restrict__ query,
                          const float* __restrict__ W_q,
                          const float* __restrict__ b_q) {
    int idx = blockIdx.x * 256 + threadIdx.x;   // < 1536
    int p = idx / EE, e = idx % EE;
    float acc = b_q[e];
    for (int i = 0; i < EE; i++)
        acc = fmaf(query[p*EE + i], W_q[i*EE + e], acc);
    g_q[idx] = acc;
}

__global__ void k_setup_A(const float* __restrict__ W_k) {
    int idx = blockIdx.x * 256 + threadIdx.x;   // < 12288
    int e = idx / HP, hp = idx % HP;
    int h = hp / PP, p = hp % PP;
    float acc = 0.f;
    #pragma unroll 4
    for (int j = 0; j < 64; j++)
        acc = fmaf(W_k[e*EE + h*64 + j], g_q[p*EE + h*64 + j], acc);
    g_A[idx] = acc * 0.125f;
}

__global__ void k_setup_misc(const float* __restrict__ b_k,
                             const float* __restrict__ w_te,
                             const float* __restrict__ b_te) {
    int tid = threadIdx.x;
    int bid = blockIdx.x;
    if (bid == 0) {
        if (tid < HP) {
            int hp = tid, h = hp / PP, p = hp % PP;
            float lin = 0.f, off = 0.f;
            for (int j = 0; j < 64; j++)
                off = fmaf(g_q[p*EE + h*64 + j], b_k[h*64 + j], off);
            off *= 0.125f;
            for (int e = 0; e < EE; e++) {
                if ((e & 7) != 0) {
                    float a = g_A[e*HP + hp];
                    lin = fmaf(w_te[e], a, lin);
                    off = fmaf(b_te[e], a, off);
                }
            }
            g_lin[hp] = lin; g_off[hp] = off;
            float bnd = off + fmaxf(lin, 0.f);
            for (int j = 0; j < NSIN; j++)
                bnd += fabsf(g_A[(8*j)*HP + hp]);
            g_bound[hp] = bnd;
        }
        if (tid < NSIN) { g_ws[tid] = w_te[8*tid]; g_bs[tid] = b_te[8*tid]; }
    } else {
        for (int idx = tid; idx < NSIN*HP; idx += 256) {
            int j = idx / HP, hp = idx % HP;
            g_Asin[idx] = g_A[(8*j)*HP + hp];
        }
    }
}

// ---------------- bconst partials ---------------------------------------
__global__ void k_bcpart(const float* __restrict__ W_o) {
    int h = blockIdx.x;           // 0..7
    int n = threadIdx.x;          // 0..255
    float acc = 0.f;
    const float* base = W_o + (size_t)(h*256 + 128)*LAT + n;
    #pragma unroll 8
    for (int c = 0; c < DD; c++)
        acc += base[(size_t)c*LAT];
    g_bcp[h*LAT + n] = acc;
}

// ---------------- W2/W3 fp16 prep (smem-tiled transpose) ----------------
__global__ void k_prepW(const float* __restrict__ W2,
                        const float* __restrict__ W3) {
    __shared__ float s_tile[64][65];
    int bid = blockIdx.x;         // 0..79
    int tid = threadIdx.x;
    int c = tid & 63, rloc = tid >> 6;

    const float* src;
    int tk, tn, src_cols;
    bool isW2 = (bid < 64);
    if (isW2) { tk = bid >> 3; tn = bid & 7; src = W2; src_cols = 512; }
    else      { int l = bid - 64; tk = l >> 1; tn = l & 1; src = W3; src_cols = 128; }

    #pragma unroll
    for (int i = 0; i < 16; i++) {
        int row = rloc + i*4;
        s_tile[row][c] = src[(size_t)(tk*64 + row)*src_cols + tn*64 + c];
    }
    __syncthreads();
    #pragma unroll
    for (int i = 0; i < 16; i++) {
        int n = rloc + i*4;
        __half h = __float2half_rn(s_tile[c][n]);
        if (isW2) g_B2[(size_t)(tn*64 + n)*512 + tk*64 + c] = h;
        else      g_B3[(size_t)(tn*64 + n)*512 + tk*64 + c] = h;
    }
}

// ---------------- K3: attention partials (scores fused in) --------------
__global__ void k_att_partial(const float* __restrict__ X,
                              const float* __restrict__ M,
                              const float* __restrict__ timesteps) {
    __shared__ float s_Asin[NSIN*HP];          // [j][hp]
    __shared__ float s_lin[HP], s_off[HP], s_m[HP];
    __shared__ float s_ws[NSIN], s_bs[NSIN];
    __shared__ float s_t[64];
    __shared__ __align__(16) float s_sin[64*SPITCH];   // [li][j]
    __shared__ __align__(16) float s_w[64*HP];
    int tid = threadIdx.x;
    int b  = blockIdx.x / SPL;
    int sp = blockIdx.x % SPL;
    int l0 = sp * LSP;
    for (int i = tid; i < NSIN*HP; i += 256) s_Asin[i] = g_Asin[i];
    if (tid < HP) { s_lin[tid] = g_lin[tid]; s_off[tid] = g_off[tid]; s_m[tid] = g_bound[tid]; }
    if (tid < NSIN) { s_ws[tid] = g_ws[tid]; s_bs[tid] = g_bs[tid]; }
    float acc[HP];
    #pragma unroll
    for (int hp = 0; hp < HP; hp++) acc[hp] = 0.f;
    int c = tid;
    int li64 = tid & 63, jg = tid >> 6;

    for (int ch = 0; ch < LSP; ch += 64) {
        if (tid < 64) s_t[tid] = timesteps[b*LL + l0 + ch + tid];
        __syncthreads();
        // stage 1: sins (each thread: one li, 16 j)
        {
            float t = s_t[li64];
            #pragma unroll
            for (int jj = 0; jj < 16; jj++) {
                int j = jg*16 + jj;
                s_sin[li64*SPITCH + j] = sin_poly(fmaf(t, s_ws[j], s_bs[j]));
            }
        }
        __syncthreads();
        // stage 2: w fill (1536 values)
        #pragma unroll
        for (int r = 0; r < 6; r++) {
            int i = tid + r*256;
            int li = i / HP, hp = i % HP;
            float a = fmaf(s_t[li], s_lin[hp], s_off[hp]) - s_m[hp];
            const float* srow = &s_sin[li*SPITCH];
            #pragma unroll 8
            for (int j = 0; j < NSIN; j++)
                a = fmaf(srow[j], s_Asin[j*HP + hp], a);
            s_w[i] = __expf(a);
        }
        __syncthreads();
        // stage 3: accumulate
        #pragma unroll 4
        for (int li = 0; li < 64; li++) {
            int l = l0 + ch + li;
            float f;
            if (c < DD) {
                float xv = X[((long)b*LL + l)*DD + c];
                float mv = M[((long)b*LL + l)*DD + c];
                f = xv * mv;
            } else {
                f = M[((long)b*LL + l)*DD + (c - DD)];
            }
            const float4* w4 = reinterpret_cast<const float4*>(&s_w[li*HP]);
            float4 w0 = w4[0], w1 = w4[1], w2 = w4[2];
            float4 w3 = w4[3], w4v = w4[4], w5 = w4[5];
            acc[0]  = fmaf(w0.x,  f, acc[0]);  acc[1]  = fmaf(w0.y,  f, acc[1]);
            acc[2]  = fmaf(w0.z,  f, acc[2]);  acc[3]  = fmaf(w0.w,  f, acc[3]);
            acc[4]  = fmaf(w1.x,  f, acc[4]);  acc[5]  = fmaf(w1.y,  f, acc[5]);
            acc[6]  = fmaf(w1.z,  f, acc[6]);  acc[7]  = fmaf(w1.w,  f, acc[7]);
            acc[8]  = fmaf(w2.x,  f, acc[8]);  acc[9]  = fmaf(w2.y,  f, acc[9]);
            acc[10] = fmaf(w2.z,  f, acc[10]); acc[11] = fmaf(w2.w,  f, acc[11]);
            acc[12] = fmaf(w3.x,  f, acc[12]); acc[13] = fmaf(w3.y,  f, acc[13]);
            acc[14] = fmaf(w3.z,  f, acc[14]); acc[15] = fmaf(w3.w,  f, acc[15]);
            acc[16] = fmaf(w4v.x, f, acc[16]); acc[17] = fmaf(w4v.y, f, acc[17]);
            acc[18] = fmaf(w4v.z, f, acc[18]); acc[19] = fmaf(w4v.w, f, acc[19]);
            acc[20] = fmaf(w5.x,  f, acc[20]); acc[21] = fmaf(w5.y,  f, acc[21]);
            acc[22] = fmaf(w5.z,  f, acc[22]); acc[23] = fmaf(w5.w,  f, acc[23]);
        }
        __syncthreads();
    }
    for (int hp = 0; hp < HP; hp++)
        g_part[(((sp*BB) + b)*HP + hp)*256 + c] = acc[hp];
}

// ---------------- K5: x1 (fused reduce), coeffs, D-matrices -------------
__global__ void k_coeffs(const float* __restrict__ W_o,
                         const float* __restrict__ W1,
                         const float* __restrict__ b1,
                         const float* __restrict__ b_o) {
    __shared__ float s_x1[HP*DD];
    __shared__ float s_cf[PP*LAT];
    int tid = threadIdx.x;
    int b = blockIdx.x;
    for (int i = tid; i < HP*DD; i += 256) {
        int hp = i / DD, c = i % DD;
        float num = 0.f, den = 0.f;
        #pragma unroll
        for (int sp = 0; sp < SPL; sp++) {
            int base = (((sp*BB) + b)*HP + hp)*256;
            num += g_part[base + c];
            den += g_part[base + 128 + c];
        }
        s_x1[i] = num / den;
    }
    __syncthreads();
    {
        int n = tid;
        float bc = b_o[n];
        #pragma unroll
        for (int j = 0; j < 8; j++) bc += g_bcp[j*LAT + n];
        float a0 = bc, a1 = bc, a2 = bc;
        for (int h = 0; h < HH; h++) {
            #pragma unroll 4
            for (int c = 0; c < DD; c++) {
                float wv = W_o[(h*256 + c)*LAT + n];
                a0 = fmaf(s_x1[(h*PP + 0)*DD + c], wv, a0);
                a1 = fmaf(s_x1[(h*PP + 1)*DD + c], wv, a1);
                a2 = fmaf(s_x1[(h*PP + 2)*DD + c], wv, a2);
            }
        }
        s_cf[0*LAT + n] = a0; s_cf[1*LAT + n] = a1; s_cf[2*LAT + n] = a2;
    }
    __syncthreads();
    for (int idx = tid; idx < 3*HID; idx += 256) {
        int k = idx / HID, j = idx % HID;
        float acc = (k == 0) ? b1[j] : 0.f;
        #pragma unroll 4
        for (int n = 0; n < LAT; n++)
            acc = fmaf(s_cf[k*LAT + n], W1[n*HID + j], acc);
        g_Dm[(b*3 + k)*HID + j] = acc;
    }
}

// ---------------- mma compute: one K=64 chunk (low reg pressure) --------
__device__ __forceinline__ void mma_chunk64(
    float acc[2][8][4], uint32_t asb, uint32_t bsb,
    int m0w, int n0w, int lane)
{
    #pragma unroll
    for (int ks = 0; ks < 4; ks++) {
        uint32_t a[2][4];
        #pragma unroll
        for (int mi = 0; mi < 2; mi++) {
            uint32_t ad = asb + (uint32_t)(m0w + mi*16 + (lane & 15)) * ROWB
                        + (uint32_t)(ks*32 + ((lane >> 4) << 4));
            LDM_X4(a[mi], ad);
        }
        #pragma unroll
        for (int nt = 0; nt < 4; nt++) {
            uint32_t bf[4];
            int rown = n0w + nt*16 + ((lane >> 4) << 3) + (lane & 7);
            uint32_t bd = bsb + (uint32_t)rown * ROWB
                        + (uint32_t)(ks*32 + (((lane >> 3) & 1) << 4));
            LDM_X4(bf, bd);
            MMA16816(acc[0][2*nt],     a[0], bf[0], bf[1]);
            MMA16816(acc[0][2*nt + 1], a[0], bf[2], bf[3]);
            MMA16816(acc[1][2*nt],     a[1], bf[0], bf[1]);
            MMA16816(acc[1][2*nt + 1], a[1], bf[2], bf[3]);
        }
    }
}

// ---------------- K6: W2 GEMM, single fp16, K=512 -----------------------
// dyn smem: 0 s_t(512) | 512 s_b2(512) | 1024 s_D(6144) |
// 7168 A bufs 2x18432 | 44032 B bufs 2x18432 | total 80896
#define SM2_DYN 80896

__global__ void __launch_bounds__(256, 2)
k_mlp2m(const float* __restrict__ yts, const float* __restrict__ b2) {
    extern __shared__ char sm[];
    float* s_t  = (float*)(sm);
    float* s_b2 = (float*)(sm + 512);
    float* s_D  = (float*)(sm + 1024);

    int tid = threadIdx.x, lane = tid & 31, wid = tid >> 5;
    int m0 = blockIdx.x * 128;
    int n0 = blockIdx.y * 128;
    int b = m0 >> 10;
    int m0w = (wid & 3) * 32;
    int n0w = (wid >> 2) * 64;

    if (tid < 128) s_t[tid] = yts[b*TT + (m0 & 1023) + tid];
    for (int i = tid; i < 3*HID; i += 256) s_D[i] = g_Dm[b*3*HID + i];
    if (tid < 128) s_b2[tid] = b2[n0 + tid];
    __syncthreads();

    uint32_t sb = smem_u32(sm);
    uint32_t as0 = sb + 7168, as1 = sb + 7168 + 18432;
    uint32_t bs0 = sb + 44032, bs1 = sb + 44032 + 18432;

    int grow = tid >> 1;
    int gkh  = (tid & 1) << 5;          // 0/32 within 64-k chunk
    float t = s_t[grow];

    float acc[2][8][4];
    #pragma unroll
    for (int mi = 0; mi < 2; mi++)
        #pragma unroll
        for (int nj = 0; nj < 8; nj++)
            #pragma unroll
            for (int q = 0; q < 4; q++) acc[mi][nj][q] = 0.f;

    // A = fp16(relu(D0 + t D1 + t^2 D2)), generated in 4-reg groups
    auto genA = [&](int kk, uint32_t asb) {
        int kloc = (kk << 6) + gkh;
        uint32_t d = asb + (uint32_t)grow*ROWB + (uint32_t)(gkh << 1);
        #pragma unroll
        for (int g4 = 0; g4 < 4; g4++) {
            uint32_t p[4];
            #pragma unroll
            for (int j2 = 0; j2 < 4; j2++) {
                float f[2];
                #pragma unroll
                for (int q = 0; q < 2; q++) {
                    int k = kloc + (g4*4 + j2)*2 + q;
                    float v = fmaf(t, fmaf(t, s_D[1024 + k], s_D[512 + k]), s_D[k]);
                    f[q] = fmaxf(v, 0.f);
                }
                p[j2] = pack2h(f[0], f[1]);
            }
            asm volatile("st.shared.v4.b32 [%0], {%1,%2,%3,%4};"
                         :: "r"(d + g4*16), "r"(p[0]), "r"(p[1]), "r"(p[2]), "r"(p[3]));
        }
    };
    auto loadB = [&](int kk, uint32_t bsb) {
        #pragma unroll
        for (int i = 0; i < 4; i++) {
            int u = tid + (i << 8);
            int n = u >> 3, q = u & 7;
            uint32_t d = bsb + (uint32_t)n*ROWB + (uint32_t)(q << 4);
            const char* s = (const char*)g_B2
                + ((size_t)(n0 + n)*512 + (size_t)kk*64)*2 + q*16;
            CP16(d, s);
        }
    };

    genA(0, as0); loadB(0, bs0); CP_COMMIT();
    for (int kk = 0; kk < NKC2; kk++) {
        int buf = kk & 1;
        if (kk + 1 < NKC2) {
            genA(kk + 1, buf ? as0 : as1);
            loadB(kk + 1, buf ? bs0 : bs1);
            CP_COMMIT();
            CP_WAIT(1);
        } else {
            CP_WAIT(0);
        }
        __syncthreads();
        mma_chunk64(acc, buf ? as1 : as0, buf ? bs1 : bs0, m0w, n0w, lane);
        __syncthreads();
    }

    // ---- epilogue: relu+bias -> fp16, smem-staged coalesced stores ----
    char* stg = sm + 7168;                   // reuse A-buf region
    const int PADR = 136;
    #pragma unroll
    for (int mi = 0; mi < 2; mi++) {
        #pragma unroll
        for (int nj = 0; nj < 8; nj++) {
            int cl = n0w + nj*8 + (lane & 3)*2;
            #pragma unroll
            for (int half = 0; half < 2; half++) {
                int r = m0w + mi*16 + (lane >> 2) + half*8;
                float f0 = fmaxf(acc[mi][nj][half*2 + 0] + s_b2[cl], 0.f);
                float f1 = fmaxf(acc[mi][nj][half*2 + 1] + s_b2[cl + 1], 0.f);
                *reinterpret_cast<uint32_t*>(stg + (r*PADR + cl)*2) = pack2h(f0, f1);
            }
        }
    }
    __syncthreads();
    #pragma unroll
    for (int ps = 0; ps < 8; ps++) {
        int u = ps*256 + tid;
        int row = u >> 4, ch = u & 15;
        uint4 v = *reinterpret_cast<uint4*>(stg + row*PADR*2 + ch*16);
        *reinterpret_cast<uint4*>((char*)g_H2 + ((size_t)(m0 + row)*HID + n0)*2 + ch*16) = v;
    }
}

// ---------------- K7: W3 GEMM, single fp16, K=512 -----------------------
// dyn smem: 0 s_b3(512) | 512 A bufs 2x18432 | 37376 B bufs 2x18432
// total 74240
#define SM3_DYN 74240

__global__ void __launch_bounds__(256, 2)
k_mlp3m(const float* __restrict__ b3, float* __restrict__ out) {
    extern __shared__ char sm[];
    float* s_b3 = (float*)(sm);

    int tid = threadIdx.x, lane = tid & 31, wid = tid >> 5;
    int m0 = blockIdx.x * 128;
    int m0w = (wid & 3) * 32;
    int n0w = (wid >> 2) * 64;

    if (tid < 128) s_b3[tid] = b3[tid];
    __syncthreads();

    uint32_t sb = smem_u32(sm);
    uint32_t as0 = sb + 512, as1 = sb + 512 + 18432;
    uint32_t bs0 = sb + 37376, bs1 = sb + 37376 + 18432;

    float acc[2][8][4];
    #pragma unroll
    for (int mi = 0; mi < 2; mi++)
        #pragma unroll
        for (int nj = 0; nj < 8; nj++)
            #pragma unroll
            for (int q = 0; q < 4; q++) acc[mi][nj][q] = 0.f;

    auto loadA = [&](int i, uint32_t asb) {
        int k0 = i << 6;
        #pragma unroll
        for (int q2 = 0; q2 < 4; q2++) {
            int u = tid + (q2 << 8);
            int row = u >> 3, q = u & 7;
            uint32_t d = asb + (uint32_t)row*ROWB + (uint32_t)(q << 4);
            const char* s = (const char*)g_H2 + ((size_t)(m0 + row)*HID + k0)*2 + q*16;
            CP16(d, s);
        }
    };
    auto loadB = [&](int i, uint32_t bsb) {
        int k0 = i << 6;
        #pragma unroll
        for (int q2 = 0; q2 < 4; q2++) {
            int u = tid + (q2 << 8);
            int n = u >> 3, q = u & 7;
            uint32_t d = bsb + (uint32_t)n*ROWB + (uint32_t)(q << 4);
            const char* s = (const char*)g_B3 + ((size_t)n*512 + k0)*2 + q*16;
            CP16(d, s);
        }
    };

    loadA(0, as0); loadB(0, bs0); CP_COMMIT();
    for (int i = 0; i < NKC3; i++) {
        int buf = i & 1;
        if (i + 1 < NKC3) {
            loadA(i + 1, buf ? as0 : as1);
            loadB(i + 1, buf ? bs0 : bs1);
            CP_COMMIT();
            CP_WAIT(1);
        } else {
            CP_WAIT(0);
        }
        __syncthreads();
        mma_chunk64(acc, buf ? as1 : as0, buf ? bs1 : bs0, m0w, n0w, lane);
        __syncthreads();
    }

    #pragma unroll
    for (int mi = 0; mi < 2; mi++) {
        #pragma unroll
        for (int nj = 0; nj < 8; nj++) {
            int cl = n0w + nj*8 + (lane & 3)*2;
            int rg = m0 + m0w + mi*16 + (lane >> 2);
            #pragma unroll
            for (int half = 0; half < 2; half++) {
                int r = rg + half*8;
                float2 v;
                v.x = acc[mi][nj][half*2 + 0] + s_b3[cl];
                v.y = acc[mi][nj][half*2 + 1] + s_b3[cl + 1];
                *reinterpret_cast<float2*>(&out[(size_t)r*DD + cl]) = v;
            }
        }
    }
}

// ---------------- launch -------------------------------------------------
extern "C" void kernel_launch(void* const* d_in, const int* in_sizes, int n_in,
                              void* d_out, int out_size) {
    const float* timesteps = (const float*)d_in[0];
    const float* X         = (const float*)d_in[1];
    const float* M         = (const float*)d_in[2];
    const float* yts       = (const float*)d_in[3];
    const float* w_te      = (const float*)d_in[4];
    const float* b_te      = (const float*)d_in[5];
    const float* query     = (const float*)d_in[6];
    const float* W_q       = (const float*)d_in[7];
    const float* b_q       = (const float*)d_in[8];
    const float* W_k       = (const float*)d_in[9];
    const float* b_k       = (const float*)d_in[10];
    const float* W_o       = (const float*)d_in[11];
    const float* b_o       = (const float*)d_in[12];
    const float* W1        = (const float*)d_in[13];
    const float* b1        = (const float*)d_in[14];
    const float* W2        = (const float*)d_in[15];
    const float* b2        = (const float*)d_in[16];
    const float* W3        = (const float*)d_in[17];
    const float* b3        = (const float*)d_in[18];
    float* out = (float*)d_out;

    cudaFuncSetAttribute(k_mlp2m, cudaFuncAttributeMaxDynamicSharedMemorySize, SM2_DYN);
    cudaFuncSetAttribute(k_mlp3m, cudaFuncAttributeMaxDynamicSharedMemorySize, SM3_DYN);

    // order chosen so the profiler's capture slot (4th launch) lands on
    // k_att_partial — the biggest unprofiled kernel.
    k_setup_q<<<6, 256>>>(query, W_q, b_q);
    k_setup_A<<<48, 256>>>(W_k);
    k_setup_misc<<<2, 256>>>(b_k, w_te, b_te);
    k_att_partial<<<SPL*BB, 256>>>(X, M, timesteps);
    k_prepW<<<80, 256>>>(W2, W3);
    k_bcpart<<<8, 256>>>(W_o);
    k_coeffs<<<BB, 256>>>(W_o, W1, b1, b_o);
    k_mlp2m<<<dim3(BB*TT/128, 4), 256, SM2_DYN>>>(yts, b2);
    k_mlp3m<<<BB*TT/128, 256, SM3_DYN>>>(b3, out);
}

// round 15
// speedup vs baseline: 1.4433x; 1.3622x over previous
#include <cuda_runtime.h>
#include <cuda_fp16.h>
#include <math.h>
#include <stdint.h>

#define BB 64
#define LL 2048
#define TT 1024
#define DD 128
#define EE 512
#define HH 8
#define PP 3
#define HP 24
#define LAT 256
#define HID 512
#define NSIN 64
#define SPL 16
#define LSP (LL/SPL)
#define NKC2 8           // mlp2: K=512 in chunks of 64
#define NKC3 8           // mlp3: K=512 in chunks of 64
#define ROWB 144         // A/B smem row bytes (64 fp16 + 8 pad)
#define SPITCH 68        // s_sin row pitch (floats): 16B-aligned rows

// ---------------- static device scratch (no allocations) ----------------
__device__ float g_q[PP*EE];
__device__ float g_A[EE*HP];
__device__ float g_lin[HP];
__device__ float g_off[HP];
__device__ float g_bound[HP];
__device__ float g_ws[NSIN];
__device__ float g_bs[NSIN];
__device__ float g_Asin[NSIN*HP];
__device__ float g_bcp[8*LAT];
__device__ float g_part[SPL*BB*HP*256];
__device__ float g_Dm[BB*3*HID];
__device__ __align__(16) __half g_B2[512*512];               // W2 fp16, [n][k]
__device__ __align__(16) __half g_B3[128*512];               // W3 fp16, [n][k]
__device__ __align__(16) __half g_H2[(size_t)BB*TT*HID];     // relu(h1@W2+b2) fp16

// ---------------- PTX helpers -------------------------------------------
__device__ __forceinline__ uint32_t smem_u32(const void* p) {
    uint32_t a;
    asm("{ .reg .u64 t; cvta.to.shared.u64 t, %1; cvt.u32.u64 %0, t; }"
        : "=r"(a) : "l"(p));
    return a;
}
__device__ __forceinline__ uint32_t pack2h(float a, float b) {
    __half2 h = __floats2half2_rn(a, b);
    return *reinterpret_cast<uint32_t*>(&h);
}
// sin via pi-reduction + deg-11 odd Taylor; |err| < 1e-7 for |x| < ~6
__device__ __forceinline__ float sin_poly(float x) {
    float xn = rintf(x * 0.31830988618f);
    float xr = fmaf(xn, -3.14159274f, x);
    xr = fmaf(xn, 8.742278e-8f, xr);
    float x2 = xr * xr;
    float p = -2.50521084e-8f;
    p = fmaf(p, x2, 2.75573192e-6f);
    p = fmaf(p, x2, -1.98412698e-4f);
    p = fmaf(p, x2, 8.33333333e-3f);
    p = fmaf(p, x2, -1.66666667e-1f);
    float s = xr * fmaf(p, x2, 1.0f);
    int ni = (int)xn;
    return __int_as_float(__float_as_int(s) ^ ((ni & 1) << 31));
}

#define CP16(dst, src) \
    asm volatile("cp.async.cg.shared.global [%0], [%1], 16;" :: "r"(dst), "l"(src))
#define CP_COMMIT() asm volatile("cp.async.commit_group;" ::: "memory")
#define CP_WAIT(n)  asm volatile("cp.async.wait_group %0;" :: "n"(n) : "memory")

#define LDM_X4(r, addr) \
    asm volatile("ldmatrix.sync.aligned.m8n8.x4.shared.b16 {%0,%1,%2,%3}, [%4];" \
        : "=r"((r)[0]), "=r"((r)[1]), "=r"((r)[2]), "=r"((r)[3]) : "r"(addr))

#define MMA16816(c, a, b0, b1) \
    asm volatile("mma.sync.aligned.m16n8k16.row.col.f32.f16.f16.f32 " \
        "{%0,%1,%2,%3}, {%4,%5,%6,%7}, {%8,%9}, {%0,%1,%2,%3};" \
        : "+f"((c)[0]), "+f"((c)[1]), "+f"((c)[2]), "+f"((c)[3]) \
        : "r"((a)[0]), "r"((a)[1]), "r"((a)[2]), "r"((a)[3]), "r"(b0), "r"(b1))

// ---------------- setup kernels -----------------------------------------
__global__ void k_setup_q(const float* __restrict__ query,
                          const float* __restrict__ W_q,
                          const float* __restrict__ b_q) {
    int idx = blockIdx.x * 256 + threadIdx.x;   // < 1536
    int p = idx / EE, e = idx % EE;
    float acc = b_q[e];
    for (int i = 0; i < EE; i++)
        acc = fmaf(query[p*EE + i], W_q[i*EE + e], acc);
    g_q[idx] = acc;
}

__global__ void k_setup_A(const float* __restrict__ W_k) {
    int idx = blockIdx.x * 256 + threadIdx.x;   // < 12288
    int e = idx / HP, hp = idx % HP;
    int h = hp / PP, p = hp % PP;
    const float4* wr = reinterpret_cast<const float4*>(W_k + e*EE + h*64);
    const float4* qr = reinterpret_cast<const float4*>(g_q + p*EE + h*64);
    float acc = 0.f;
    #pragma unroll
    for (int j4 = 0; j4 < 16; j4++) {
        float4 w = wr[j4], q = qr[j4];
        acc = fmaf(w.x, q.x, acc);
        acc = fmaf(w.y, q.y, acc);
        acc = fmaf(w.z, q.z, acc);
        acc = fmaf(w.w, q.w, acc);
    }
    g_A[idx] = acc * 0.125f;
}

__global__ void k_setup_misc(const float* __restrict__ b_k,
                             const float* __restrict__ w_te,
                             const float* __restrict__ b_te) {
    int tid = threadIdx.x;
    int bid = blockIdx.x;
    if (bid == 0) {
        if (tid < HP) {
            int hp = tid, h = hp / PP, p = hp % PP;
            float lin = 0.f, off = 0.f;
            for (int j = 0; j < 64; j++)
                off = fmaf(g_q[p*EE + h*64 + j], b_k[h*64 + j], off);
            off *= 0.125f;
            for (int e = 0; e < EE; e++) {
                if ((e & 7) != 0) {
                    float a = g_A[e*HP + hp];
                    lin = fmaf(w_te[e], a, lin);
                    off = fmaf(b_te[e], a, off);
                }
            }
            g_lin[hp] = lin; g_off[hp] = off;
            float bnd = off + fmaxf(lin, 0.f);
            for (int j = 0; j < NSIN; j++)
                bnd += fabsf(g_A[(8*j)*HP + hp]);
            g_bound[hp] = bnd;
        }
        if (tid < NSIN) { g_ws[tid] = w_te[8*tid]; g_bs[tid] = b_te[8*tid]; }
    } else {
        for (int idx = tid; idx < NSIN*HP; idx += 256) {
            int j = idx / HP, hp = idx % HP;
            g_Asin[idx] = g_A[(8*j)*HP + hp];
        }
    }
}

// ---------------- W2/W3 fp16 prep + bconst partials (merged) ------------
__global__ void k_prepW(const float* __restrict__ W2,
                        const float* __restrict__ W3,
                        const float* __restrict__ W_o) {
    __shared__ float s_tile[64][65];
    int bid = blockIdx.x;         // 0..87
    int tid = threadIdx.x;

    if (bid >= 80) {              // bconst partials, h = bid - 80
        int h = bid - 80;
        int n = tid;
        float acc = 0.f;
        const float* base = W_o + (size_t)(h*256 + 128)*LAT + n;
        #pragma unroll 8
        for (int c = 0; c < DD; c++)
            acc += base[(size_t)c*LAT];
        g_bcp[h*LAT + n] = acc;
        return;
    }

    int c = tid & 63, rloc = tid >> 6;
    const float* src;
    int tk, tn, src_cols;
    bool isW2 = (bid < 64);
    if (isW2) { tk = bid >> 3; tn = bid & 7; src = W2; src_cols = 512; }
    else      { int l = bid - 64; tk = l >> 1; tn = l & 1; src = W3; src_cols = 128; }

    #pragma unroll
    for (int i = 0; i < 16; i++) {
        int row = rloc + i*4;
        s_tile[row][c] = src[(size_t)(tk*64 + row)*src_cols + tn*64 + c];
    }
    __syncthreads();
    #pragma unroll
    for (int i = 0; i < 16; i++) {
        int n = rloc + i*4;
        __half h = __float2half_rn(s_tile[c][n]);
        if (isW2) g_B2[(size_t)(tn*64 + n)*512 + tk*64 + c] = h;
        else      g_B3[(size_t)(tn*64 + n)*512 + tk*64 + c] = h;
    }
}

// ---------------- K3: attention partials (scores fused in) --------------
__global__ void k_att_partial(const float* __restrict__ X,
                              const float* __restrict__ M,
                              const float* __restrict__ timesteps) {
    __shared__ float s_Asin[NSIN*HP];          // [j][hp]
    __shared__ float s_lin[HP], s_off[HP], s_m[HP];
    __shared__ float s_ws[NSIN], s_bs[NSIN];
    __shared__ float s_t[64];
    __shared__ __align__(16) float s_sin[64*SPITCH];   // [li][j]
    __shared__ __align__(16) float s_w[64*HP];
    int tid = threadIdx.x;
    int b  = blockIdx.x / SPL;
    int sp = blockIdx.x % SPL;
    int l0 = sp * LSP;
    for (int i = tid; i < NSIN*HP; i += 256) s_Asin[i] = g_Asin[i];
    if (tid < HP) { s_lin[tid] = g_lin[tid]; s_off[tid] = g_off[tid]; s_m[tid] = g_bound[tid]; }
    if (tid < NSIN) { s_ws[tid] = g_ws[tid]; s_bs[tid] = g_bs[tid]; }
    float acc[HP];
    #pragma unroll
    for (int hp = 0; hp < HP; hp++) acc[hp] = 0.f;
    int c = tid;
    int li64 = tid & 63, jg = tid >> 6;

    for (int ch = 0; ch < LSP; ch += 64) {
        if (tid < 64) s_t[tid] = timesteps[b*LL + l0 + ch + tid];
        __syncthreads();
        // stage 1: sins (each thread: one li, 16 j)
        {
            float t = s_t[li64];
            #pragma unroll
            for (int jj = 0; jj < 16; jj++) {
                int j = jg*16 + jj;
                s_sin[li64*SPITCH + j] = sin_poly(fmaf(t, s_ws[j], s_bs[j]));
            }
        }
        __syncthreads();
        // stage 2: w fill (1536 values)
        #pragma unroll
        for (int r = 0; r < 6; r++) {
            int i = tid + r*256;
            int li = i / HP, hp = i % HP;
            float a = fmaf(s_t[li], s_lin[hp], s_off[hp]) - s_m[hp];
            const float* srow = &s_sin[li*SPITCH];
            #pragma unroll 8
            for (int j = 0; j < NSIN; j++)
                a = fmaf(srow[j], s_Asin[j*HP + hp], a);
            s_w[i] = __expf(a);
        }
        __syncthreads();
        // stage 3: accumulate
        #pragma unroll 4
        for (int li = 0; li < 64; li++) {
            int l = l0 + ch + li;
            float f;
            if (c < DD) {
                float xv = X[((long)b*LL + l)*DD + c];
                float mv = M[((long)b*LL + l)*DD + c];
                f = xv * mv;
            } else {
                f = M[((long)b*LL + l)*DD + (c - DD)];
            }
            const float4* w4 = reinterpret_cast<const float4*>(&s_w[li*HP]);
            float4 w0 = w4[0], w1 = w4[1], w2 = w4[2];
            float4 w3 = w4[3], w4v = w4[4], w5 = w4[5];
            acc[0]  = fmaf(w0.x,  f, acc[0]);  acc[1]  = fmaf(w0.y,  f, acc[1]);
            acc[2]  = fmaf(w0.z,  f, acc[2]);  acc[3]  = fmaf(w0.w,  f, acc[3]);
            acc[4]  = fmaf(w1.x,  f, acc[4]);  acc[5]  = fmaf(w1.y,  f, acc[5]);
            acc[6]  = fmaf(w1.z,  f, acc[6]);  acc[7]  = fmaf(w1.w,  f, acc[7]);
            acc[8]  = fmaf(w2.x,  f, acc[8]);  acc[9]  = fmaf(w2.y,  f, acc[9]);
            acc[10] = fmaf(w2.z,  f, acc[10]); acc[11] = fmaf(w2.w,  f, acc[11]);
            acc[12] = fmaf(w3.x,  f, acc[12]); acc[13] = fmaf(w3.y,  f, acc[13]);
            acc[14] = fmaf(w3.z,  f, acc[14]); acc[15] = fmaf(w3.w,  f, acc[15]);
            acc[16] = fmaf(w4v.x, f, acc[16]); acc[17] = fmaf(w4v.y, f, acc[17]);
            acc[18] = fmaf(w4v.z, f, acc[18]); acc[19] = fmaf(w4v.w, f, acc[19]);
            acc[20] = fmaf(w5.x,  f, acc[20]); acc[21] = fmaf(w5.y,  f, acc[21]);
            acc[22] = fmaf(w5.z,  f, acc[22]); acc[23] = fmaf(w5.w,  f, acc[23]);
        }
        __syncthreads();
    }
    for (int hp = 0; hp < HP; hp++)
        g_part[(((sp*BB) + b)*HP + hp)*256 + c] = acc[hp];
}

// ---------------- K5: coeffs/D-matrices, 1024 thr, split-K --------------
__global__ void __launch_bounds__(1024)
k_coeffs(const float* __restrict__ W_o,
         const float* __restrict__ W1,
         const float* __restrict__ b1,
         const float* __restrict__ b_o) {
    __shared__ float s_x1[HP*DD];       // 12 KB
    __shared__ float s_cf[PP*LAT];      // 3 KB
    __shared__ float s_scr[6144];       // 24 KB (reused)
    int tid = threadIdx.x;
    int b = blockIdx.x;

    // stage A: x1 (fused reduce over SPL)
    for (int i = tid; i < HP*DD; i += 1024) {
        int hp = i / DD, c = i % DD;
        float num = 0.f, den = 0.f;
        #pragma unroll
        for (int sp = 0; sp < SPL; sp++) {
            int base = (((sp*BB) + b)*HP + hp)*256;
            num += g_part[base + c];
            den += g_part[base + 128 + c];
        }
        s_x1[i] = num / den;
    }
    __syncthreads();

    // stage B: cf partials, quarter q handles h = 2q..2q+1
    {
        int q = tid >> 8, n = tid & 255;
        float a0 = 0.f, a1 = 0.f, a2 = 0.f;
        #pragma unroll
        for (int hh = 0; hh < 2; hh++) {
            int h = q*2 + hh;
            const float* wo = W_o + (size_t)(h*256)*LAT + n;
            const float* x0 = &s_x1[(h*PP + 0)*DD];
            const float* x1p = &s_x1[(h*PP + 1)*DD];
            const float* x2 = &s_x1[(h*PP + 2)*DD];
            #pragma unroll 4
            for (int c = 0; c < DD; c++) {
                float wv = wo[(size_t)c*LAT];
                a0 = fmaf(x0[c], wv, a0);
                a1 = fmaf(x1p[c], wv, a1);
                a2 = fmaf(x2[c], wv, a2);
            }
        }
        s_scr[(q*3 + 0)*256 + n] = a0;
        s_scr[(q*3 + 1)*256 + n] = a1;
        s_scr[(q*3 + 2)*256 + n] = a2;
    }
    __syncthreads();

    // stage B2: reduce + bias
    if (tid < LAT) {
        int n = tid;
        float bc = b_o[n];
        #pragma unroll
        for (int j = 0; j < 8; j++) bc += g_bcp[j*LAT + n];
        #pragma unroll
        for (int p = 0; p < PP; p++) {
            float v = bc;
            #pragma unroll
            for (int q = 0; q < 4; q++) v += s_scr[(q*3 + p)*256 + n];
            s_cf[p*LAT + n] = v;
        }
    }
    __syncthreads();

    // stage C: Dm partials, quarter q handles n in [64q, 64q+64)
    {
        int q = tid >> 8, jj = tid & 255;
        #pragma unroll
        for (int k = 0; k < PP; k++) {
            const float* cf = &s_cf[k*LAT];
            #pragma unroll
            for (int j2 = 0; j2 < 2; j2++) {
                int j = j2*256 + jj;
                float a = 0.f;
                #pragma unroll 8
                for (int nn = q*64; nn < q*64 + 64; nn++)
                    a = fmaf(cf[nn], W1[(size_t)nn*HID + j], a);
                s_scr[(k*2 + j2)*1024 + q*256 + jj] = a;
            }
        }
    }
    __syncthreads();

    // stage C2: reduce + bias -> g_Dm
    for (int o = tid; o < PP*HID; o += 1024) {
        int k = o / HID, j = o % HID;
        int j2 = j >> 8, jj = j & 255;
        float a = (k == 0) ? b1[j] : 0.f;
        #pragma unroll
        for (int q = 0; q < 4; q++)
            a += s_scr[(k*2 + j2)*1024 + q*256 + jj];
        g_Dm[(b*3 + k)*HID + j] = a;
    }
}

// ---------------- mma compute: one K=64 chunk (low reg pressure) --------
__device__ __forceinline__ void mma_chunk64(
    float acc[2][8][4], uint32_t asb, uint32_t bsb,
    int m0w, int n0w, int lane)
{
    #pragma unroll
    for (int ks = 0; ks < 4; ks++) {
        uint32_t a[2][4];
        #pragma unroll
        for (int mi = 0; mi < 2; mi++) {
            uint32_t ad = asb + (uint32_t)(m0w + mi*16 + (lane & 15)) * ROWB
                        + (uint32_t)(ks*32 + ((lane >> 4) << 4));
            LDM_X4(a[mi], ad);
        }
        #pragma unroll
        for (int nt = 0; nt < 4; nt++) {
            uint32_t bf[4];
            int rown = n0w + nt*16 + ((lane >> 4) << 3) + (lane & 7);
            uint32_t bd = bsb + (uint32_t)rown * ROWB
                        + (uint32_t)(ks*32 + (((lane >> 3) & 1) << 4));
            LDM_X4(bf, bd);
            MMA16816(acc[0][2*nt],     a[0], bf[0], bf[1]);
            MMA16816(acc[0][2*nt + 1], a[0], bf[2], bf[3]);
            MMA16816(acc[1][2*nt],     a[1], bf[0], bf[1]);
            MMA16816(acc[1][2*nt + 1], a[1], bf[2], bf[3]);
        }
    }
}

// ---------------- K6: W2 GEMM, single fp16, K=512 -----------------------
#define SM2_DYN 80896

__global__ void __launch_bounds__(256, 2)
k_mlp2m(const float* __restrict__ yts, const float* __restrict__ b2) {
    extern __shared__ char sm[];
    float* s_t  = (float*)(sm);
    float* s_b2 = (float*)(sm + 512);
    float* s_D  = (float*)(sm + 1024);

    int tid = threadIdx.x, lane = tid & 31, wid = tid >> 5;
    int m0 = blockIdx.x * 128;
    int n0 = blockIdx.y * 128;
    int b = m0 >> 10;
    int m0w = (wid & 3) * 32;
    int n0w = (wid >> 2) * 64;

    if (tid < 128) s_t[tid] = yts[b*TT + (m0 & 1023) + tid];
    for (int i = tid; i < 3*HID; i += 256) s_D[i] = g_Dm[b*3*HID + i];
    if (tid < 128) s_b2[tid] = b2[n0 + tid];
    __syncthreads();

    uint32_t sb = smem_u32(sm);
    uint32_t as0 = sb + 7168, as1 = sb + 7168 + 18432;
    uint32_t bs0 = sb + 44032, bs1 = sb + 44032 + 18432;

    int grow = tid >> 1;
    int gkh  = (tid & 1) << 5;
    float t = s_t[grow];

    float acc[2][8][4];
    #pragma unroll
    for (int mi = 0; mi < 2; mi++)
        #pragma unroll
        for (int nj = 0; nj < 8; nj++)
            #pragma unroll
            for (int q = 0; q < 4; q++) acc[mi][nj][q] = 0.f;

    auto genA = [&](int kk, uint32_t asb) {
        int kloc = (kk << 6) + gkh;
        uint32_t d = asb + (uint32_t)grow*ROWB + (uint32_t)(gkh << 1);
        #pragma unroll
        for (int g4 = 0; g4 < 4; g4++) {
            uint32_t p[4];
            #pragma unroll
            for (int j2 = 0; j2 < 4; j2++) {
                float f[2];
                #pragma unroll
                for (int q = 0; q < 2; q++) {
                    int k = kloc + (g4*4 + j2)*2 + q;
                    float v = fmaf(t, fmaf(t, s_D[1024 + k], s_D[512 + k]), s_D[k]);
                    f[q] = fmaxf(v, 0.f);
                }
                p[j2] = pack2h(f[0], f[1]);
            }
            asm volatile("st.shared.v4.b32 [%0], {%1,%2,%3,%4};"
                         :: "r"(d + g4*16), "r"(p[0]), "r"(p[1]), "r"(p[2]), "r"(p[3]));
        }
    };
    auto loadB = [&](int kk, uint32_t bsb) {
        #pragma unroll
        for (int i = 0; i < 4; i++) {
            int u = tid + (i << 8);
            int n = u >> 3, q = u & 7;
            uint32_t d = bsb + (uint32_t)n*ROWB + (uint32_t)(q << 4);
            const char* s = (const char*)g_B2
                + ((size_t)(n0 + n)*512 + (size_t)kk*64)*2 + q*16;
            CP16(d, s);
        }
    };

    genA(0, as0); loadB(0, bs0); CP_COMMIT();
    for (int kk = 0; kk < NKC2; kk++) {
        int buf = kk & 1;
        if (kk + 1 < NKC2) {
            genA(kk + 1, buf ? as0 : as1);
            loadB(kk + 1, buf ? bs0 : bs1);
            CP_COMMIT();
            CP_WAIT(1);
        } else {
            CP_WAIT(0);
        }
        __syncthreads();
        mma_chunk64(acc, buf ? as1 : as0, buf ? bs1 : bs0, m0w, n0w, lane);
        __syncthreads();
    }

    char* stg = sm + 7168;
    const int PADR = 136;
    #pragma unroll
    for (int mi = 0; mi < 2; mi++) {
        #pragma unroll
        for (int nj = 0; nj < 8; nj++) {
            int cl = n0w + nj*8 + (lane & 3)*2;
            #pragma unroll
            for (int half = 0; half < 2; half++) {
                int r = m0w + mi*16 + (lane >> 2) + half*8;
                float f0 = fmaxf(acc[mi][nj][half*2 + 0] + s_b2[cl], 0.f);
                float f1 = fmaxf(acc[mi][nj][half*2 + 1] + s_b2[cl + 1], 0.f);
                *reinterpret_cast<uint32_t*>(stg + (r*PADR + cl)*2) = pack2h(f0, f1);
            }
        }
    }
    __syncthreads();
    #pragma unroll
    for (int ps = 0; ps < 8; ps++) {
        int u = ps*256 + tid;
        int row = u >> 4, ch = u & 15;
        uint4 v = *reinterpret_cast<uint4*>(stg + row*PADR*2 + ch*16);
        *reinterpret_cast<uint4*>((char*)g_H2 + ((size_t)(m0 + row)*HID + n0)*2 + ch*16) = v;
    }
}

// ---------------- K7: W3 GEMM, single fp16, K=512 -----------------------
#define SM3_DYN 74240

__global__ void __launch_bounds__(256, 2)
k_mlp3m(const float* __restrict__ b3, float* __restrict__ out) {
    extern __shared__ char sm[];
    float* s_b3 = (float*)(sm);

    int tid = threadIdx.x, lane = tid & 31, wid = tid >> 5;
    int m0 = blockIdx.x * 128;
    int m0w = (wid & 3) * 32;
    int n0w = (wid >> 2) * 64;

    if (tid < 128) s_b3[tid] = b3[tid];
    __syncthreads();

    uint32_t sb = smem_u32(sm);
    uint32_t as0 = sb + 512, as1 = sb + 512 + 18432;
    uint32_t bs0 = sb + 37376, bs1 = sb + 37376 + 18432;

    float acc[2][8][4];
    #pragma unroll
    for (int mi = 0; mi < 2; mi++)
        #pragma unroll
        for (int nj = 0; nj < 8; nj++)
            #pragma unroll
            for (int q = 0; q < 4; q++) acc[mi][nj][q] = 0.f;

    auto loadA = [&](int i, uint32_t asb) {
        int k0 = i << 6;
        #pragma unroll
        for (int q2 = 0; q2 < 4; q2++) {
            int u = tid + (q2 << 8);
            int row = u >> 3, q = u & 7;
            uint32_t d = asb + (uint32_t)row*ROWB + (uint32_t)(q << 4);
            const char* s = (const char*)g_H2 + ((size_t)(m0 + row)*HID + k0)*2 + q*16;
            CP16(d, s);
        }
    };
    auto loadB = [&](int i, uint32_t bsb) {
        int k0 = i << 6;
        #pragma unroll
        for (int q2 = 0; q2 < 4; q2++) {
            int u = tid + (q2 << 8);
            int n = u >> 3, q = u & 7;
            uint32_t d = bsb + (uint32_t)n*ROWB + (uint32_t)(q << 4);
            const char* s = (const char*)g_B3 + ((size_t)n*512 + k0)*2 + q*16;
            CP16(d, s);
        }
    };

    loadA(0, as0); loadB(0, bs0); CP_COMMIT();
    for (int i = 0; i < NKC3; i++) {
        int buf = i & 1;
        if (i + 1 < NKC3) {
            loadA(i + 1, buf ? as0 : as1);
            loadB(i + 1, buf ? bs0 : bs1);
            CP_COMMIT();
            CP_WAIT(1);
        } else {
            CP_WAIT(0);
        }
        __syncthreads();
        mma_chunk64(acc, buf ? as1 : as0, buf ? bs1 : bs0, m0w, n0w, lane);
        __syncthreads();
    }

    #pragma unroll
    for (int mi = 0; mi < 2; mi++) {
        #pragma unroll
        for (int nj = 0; nj < 8; nj++) {
            int cl = n0w + nj*8 + (lane & 3)*2;
            int rg = m0 + m0w + mi*16 + (lane >> 2);
            #pragma unroll
            for (int half = 0; half < 2; half++) {
                int r = rg + half*8;
                float2 v;
                v.x = acc[mi][nj][half*2 + 0] + s_b3[cl];
                v.y = acc[mi][nj][half*2 + 1] + s_b3[cl + 1];
                *reinterpret_cast<float2*>(&out[(size_t)r*DD + cl]) = v;
            }
        }
    }
}

// ---------------- launch -------------------------------------------------
extern "C" void kernel_launch(void* const* d_in, const int* in_sizes, int n_in,
                              void* d_out, int out_size) {
    const float* timesteps = (const float*)d_in[0];
    const float* X         = (const float*)d_in[1];
    const float* M         = (const float*)d_in[2];
    const float* yts       = (const float*)d_in[3];
    const float* w_te      = (const float*)d_in[4];
    const float* b_te      = (const float*)d_in[5];
    const float* query     = (const float*)d_in[6];
    const float* W_q       = (const float*)d_in[7];
    const float* b_q       = (const float*)d_in[8];
    const float* W_k       = (const float*)d_in[9];
    const float* b_k       = (const float*)d_in[10];
    const float* W_o       = (const float*)d_in[11];
    const float* b_o       = (const float*)d_in[12];
    const float* W1        = (const float*)d_in[13];
    const float* b1        = (const float*)d_in[14];
    const float* W2        = (const float*)d_in[15];
    const float* b2        = (const float*)d_in[16];
    const float* W3        = (const float*)d_in[17];
    const float* b3        = (const float*)d_in[18];
    float* out = (float*)d_out;

    cudaFuncSetAttribute(k_mlp2m, cudaFuncAttributeMaxDynamicSharedMemorySize, SM2_DYN);
    cudaFuncSetAttribute(k_mlp3m, cudaFuncAttributeMaxDynamicSharedMemorySize, SM3_DYN);

    // slot 4 (profiler capture) = k_att_partial
    k_setup_q<<<6, 256>>>(query, W_q, b_q);
    k_setup_A<<<48, 256>>>(W_k);
    k_setup_misc<<<2, 256>>>(b_k, w_te, b_te);
    k_att_partial<<<SPL*BB, 256>>>(X, M, timesteps);
    k_prepW<<<88, 256>>>(W2, W3, W_o);
    k_coeffs<<<BB, 1024>>>(W_o, W1, b1, b_o);
    k_mlp2m<<<dim3(BB*TT/128, 4), 256, SM2_DYN>>>(yts, b2);
    k_mlp3m<<<BB*TT/128, 256, SM3_DYN>>>(b3, out);
}